// round 10
// baseline (speedup 1.0000x reference)
#include <cuda_runtime.h>
#include <cstdint>
#include <math.h>

#define BB 4
#define CC 256
#define NPTS 16384
#define MTOT 65536
#define HC 64
#define NOUT 320
#define NQ 256
#define NS0 32
#define NS1 64

#define OFF_QUERY 0
#define OFF_QF    3072
#define OFF_PRED  265216
#define OFF_M     265256
#define OFF_G0    17042472
#define OFF_G1    17075240

__device__ float g_W[CC * NOUT];
__device__ float g_Y[HC * MTOT];   // column-major [col][m]
__device__ float g_mean[NOUT];
__device__ float g_rstd[NOUT];
__device__ float g_hpart[256 * HC];
__device__ int   g_label[BB];
__device__ float g_qval[MTOT];
__device__ int   g_qidx[BB * NQ];

// ---------- fast gelu (1e-3-tolerance outputs only) ----------
__device__ __forceinline__ float gelu_fast(float x) {
    float x3 = x * x * x;
    float t = tanhf(0.7978845608028654f * (x + 0.044715f * x3));
    return 0.5f * x * (1.0f + t);
}

// ---------- XLA FastTanh (rational, separate mul/add, fdiv) ----------
__device__ __forceinline__ float xla_tanhf(float x) {
    if (fabsf(x) < 0.0004f) return x;
    float xc = fminf(fmaxf(x, -7.90531110763549805f), 7.90531110763549805f);
    float x2 = __fmul_rn(xc, xc);
    float p = -2.76076847742355e-16f;
    p = __fadd_rn(__fmul_rn(p, x2), 2.00018790482477e-13f);
    p = __fadd_rn(__fmul_rn(p, x2), -8.60467152213735e-11f);
    p = __fadd_rn(__fmul_rn(p, x2), 5.12229709037114e-08f);
    p = __fadd_rn(__fmul_rn(p, x2), 1.48572235717979e-05f);
    p = __fadd_rn(__fmul_rn(p, x2), 6.37261928875436e-04f);
    p = __fadd_rn(__fmul_rn(p, x2), 4.89352455891786e-03f);
    float num = __fmul_rn(xc, p);
    float q = 1.19825839466702e-06f;
    q = __fadd_rn(__fmul_rn(q, x2), 1.18534705686654e-04f);
    q = __fadd_rn(__fmul_rn(q, x2), 2.26843463243900e-03f);
    q = __fadd_rn(__fmul_rn(q, x2), 4.89352518554385e-03f);
    return __fdiv_rn(num, q);
}

// jax.nn.gelu(approximate=True) exact op order: x3=(x*x)*x; a=x+0.044715*x3;
// t=tanh(c*a); cdf=0.5*(1+t); x*cdf
__device__ __forceinline__ float gelu_exact(float x) {
    float x2 = __fmul_rn(x, x);
    float x3 = __fmul_rn(x2, x);
    float a  = __fadd_rn(x, __fmul_rn(0.044715f, x3));
    float t  = xla_tanhf(__fmul_rn(0.7978845608028654f, a));
    float cdf = __fmul_rn(0.5f, __fadd_rn(1.0f, t));
    return __fmul_rn(x, cdf);
}

// ((x-mean)*rstd)*gamma + beta, each separately rounded
__device__ __forceinline__ float bn_exact(float x, float mean, float rstd,
                                          float ga, float be) {
    return __fadd_rn(__fmul_rn(__fmul_rn(__fsub_rn(x, mean), rstd), ga), be);
}

// ---------- Eigen pexp<float> replica ----------
__device__ __forceinline__ float eigen_expf(float x) {
    x = fminf(fmaxf(x, -88.723164f), 88.723164f);
    float m = floorf(__fmaf_rn(x, 1.44269504088896341f, 0.5f));
    float r = __fmaf_rn(m, -0.693359375f, x);
    r = __fmaf_rn(m, 2.12194440e-4f, r);
    float r2 = __fmul_rn(r, r);
    float p = 1.9875691500e-4f;
    p = __fmaf_rn(p, r, 1.3981999507e-3f);
    p = __fmaf_rn(p, r, 8.3334519073e-3f);
    p = __fmaf_rn(p, r, 4.1665795894e-2f);
    p = __fmaf_rn(p, r, 1.6666665459e-1f);
    p = __fmaf_rn(p, r, 5.0000001201e-1f);
    p = __fmaf_rn(p, r2, r);
    p = __fadd_rn(p, 1.0f);
    int mi = (int)m; if (mi < -126) mi = -126; if (mi > 127) mi = 127;
    return __fmul_rn(p, __int_as_float((unsigned)(mi + 127) << 23));
}

// ---------- Eigen plog<float> replica (positive normal input) ----------
__device__ __forceinline__ float eigen_logf(float x) {
    int bits = __float_as_int(x);
    float e = (float)(((bits >> 23) & 0xff) - 126);
    float mant = __int_as_float((bits & 0x807fffff) | 0x3f000000);  // [0.5,1)
    if (mant < 0.707106781186547524f) {
        e = __fsub_rn(e, 1.0f);
        mant = __fadd_rn(__fsub_rn(mant, 1.0f), mant);
    } else {
        mant = __fsub_rn(mant, 1.0f);
    }
    float x2 = __fmul_rn(mant, mant);
    float x3 = __fmul_rn(x2, mant);
    float y = 7.0376836292e-2f;
    y = __fmaf_rn(y, mant, -1.1514610310e-1f);
    y = __fmaf_rn(y, mant, 1.1676998740e-1f);
    y = __fmaf_rn(y, mant, -1.2420140846e-1f);
    y = __fmaf_rn(y, mant, 1.4249322787e-1f);
    y = __fmaf_rn(y, mant, -1.6668057665e-1f);
    y = __fmaf_rn(y, mant, 2.0000714765e-1f);
    y = __fmaf_rn(y, mant, -2.4999993993e-1f);
    y = __fmaf_rn(y, mant, 3.3333331174e-1f);
    y = __fmul_rn(y, x3);
    y = __fmaf_rn(e, -2.12194440e-4f, y);
    y = __fsub_rn(y, __fmul_rn(x2, 0.5f));
    float r = __fadd_rn(mant, y);
    return __fmaf_rn(e, 0.693359375f, r);
}

// ---------- pack W = [w1 | wm] ----------
__global__ void kpack(const float* __restrict__ w1, const float* __restrict__ wm) {
    int i = blockIdx.x * 256 + threadIdx.x;
    int c = i / NOUT, k = i - c * NOUT;
    g_W[i] = (k < HC) ? w1[c * HC + k] : wm[c * CC + (k - HC)];
}

// ---------- fused GEMM 65536x320x256, sequential-k FMA chain ----------
__global__ void __launch_bounds__(256) kgemm(const float* __restrict__ feats,
                                             float* __restrict__ out) {
    __shared__ float As[16][128];
    __shared__ __align__(16) float Bs[16][64];
    int bm = blockIdx.x, bn = blockIdx.y;
    int tid = threadIdx.x;
    int b  = bm >> 7;
    int n0 = (bm & 127) << 7;
    const float* Ab = feats + (size_t)b * (CC * NPTS) + n0;
    const float* Wb = g_W + bn * 64;
    int mlane = tid & 15;
    int ngrp  = tid >> 4;
    float acc[8][4];
#pragma unroll
    for (int i = 0; i < 8; i++)
#pragma unroll
        for (int j = 0; j < 4; j++) acc[i][j] = 0.0f;

    for (int kt = 0; kt < CC; kt += 16) {
#pragma unroll
        for (int i = 0; i < 8; i++) {
            int l = tid + i * 256; int k = l >> 7, mm = l & 127;
            As[k][mm] = Ab[(size_t)(kt + k) * NPTS + mm];
        }
#pragma unroll
        for (int i = 0; i < 4; i++) {
            int l = tid + i * 256; int k = l >> 6, nn = l & 63;
            Bs[k][nn] = Wb[(kt + k) * NOUT + nn];
        }
        __syncthreads();
#pragma unroll
        for (int k = 0; k < 16; k++) {
            float a[8];
#pragma unroll
            for (int i = 0; i < 8; i++) a[i] = As[k][mlane + i * 16];
            float4 b4 = *(const float4*)&Bs[k][ngrp * 4];
#pragma unroll
            for (int i = 0; i < 8; i++) {
                acc[i][0] = __fmaf_rn(a[i], b4.x, acc[i][0]);
                acc[i][1] = __fmaf_rn(a[i], b4.y, acc[i][1]);
                acc[i][2] = __fmaf_rn(a[i], b4.z, acc[i][2]);
                acc[i][3] = __fmaf_rn(a[i], b4.w, acc[i][3]);
            }
        }
        __syncthreads();
    }

    int m0 = bm << 7;
    if (bn == 0) {
#pragma unroll
        for (int i = 0; i < 8; i++) {
            int m = m0 + mlane + i * 16;
#pragma unroll
            for (int j = 0; j < 4; j++)
                g_Y[(size_t)(ngrp * 4 + j) * MTOT + m] = acc[i][j];
        }
    } else {
        float* mo = out + OFF_M;
#pragma unroll
        for (int i = 0; i < 8; i++) {
            int n = n0 + mlane + i * 16;
#pragma unroll
            for (int j = 0; j < 4; j++) {
                int d = (bn - 1) * 64 + ngrp * 4 + j;
                mo[((size_t)(b * CC + d)) * NPTS + n] = acc[i][j];
            }
        }
    }
}

// ---------- EXACT y-branch stats: sequential two-pass per channel ----------
__global__ void kstats_y() {
    int j = blockIdx.x * 32 + threadIdx.x;    // <<<2,32>>>
    const float* p = g_Y + (size_t)j * MTOT;
    float acc = 0.0f;
#pragma unroll 8
    for (int i = 0; i < MTOT; i++) acc = __fadd_rn(acc, p[i]);
    float mean = __fdiv_rn(acc, 65536.0f);
    float v = 0.0f;
#pragma unroll 8
    for (int i = 0; i < MTOT; i++) {
        float d = __fsub_rn(p[i], mean);
        v = __fadd_rn(v, __fmul_rn(d, d));
    }
    float var = __fdiv_rn(v, 65536.0f);
    g_mean[j] = mean;
    g_rstd[j] = __fdiv_rn(1.0f, __fsqrt_rn(__fadd_rn(var, 1e-5f)));
}

// ---------- fast tree stats for m channels (1e-3 tolerance) ----------
__global__ void ksum_m(const float* __restrict__ out) {
    int ch = HC + blockIdx.x;
    int tid = threadIdx.x;
    __shared__ float s1[256], s2[256];
    float a = 0.0f, q = 0.0f;
    int d = ch - HC;
    for (int b = 0; b < BB; b++) {
        const float* p = out + OFF_M + ((size_t)(b * CC + d)) * NPTS;
        for (int i = tid; i < NPTS; i += 256) { float v = p[i]; a += v; q += v * v; }
    }
    s1[tid] = a; s2[tid] = q; __syncthreads();
    for (int s = 128; s > 0; s >>= 1) {
        if (tid < s) { s1[tid] += s1[tid + s]; s2[tid] += s2[tid + s]; }
        __syncthreads();
    }
    if (tid == 0) {
        float mean = s1[0] * (1.0f / 65536.0f);
        float var  = s2[0] * (1.0f / 65536.0f) - mean * mean;
        g_mean[ch] = mean;
        g_rstd[ch] = rsqrtf(var + 1e-5f);
    }
}

// ---------- gelu(BN(m)) in-place ----------
__global__ void knorm(float* __restrict__ out, const float* __restrict__ gm,
                      const float* __restrict__ bm) {
    int i4 = blockIdx.x * 256 + threadIdx.x;
    size_t base = (size_t)i4 * 4;
    int d = (int)((base >> 14) & 255);
    float mean = g_mean[HC + d], rstd = g_rstd[HC + d];
    float ga = gm[d], be = bm[d];
    float* mo = out + OFF_M;
    float4 v = *(float4*)(mo + base);
    v.x = gelu_fast((v.x - mean) * rstd * ga + be);
    v.y = gelu_fast((v.y - mean) * rstd * ga + be);
    v.z = gelu_fast((v.z - mean) * rstd * ga + be);
    v.w = gelu_fast((v.w - mean) * rstd * ga + be);
    *(float4*)(mo + base) = v;
}

// ---------- partial h sums (fast path, for preds/label only) ----------
__global__ void khpart(const float* __restrict__ g1, const float* __restrict__ b1) {
    int blk = blockIdx.x;
    int tid = threadIdx.x;
    int lane = tid & 31, w = tid >> 5;
    int b = blk >> 6, nc = blk & 63;
    int m0 = b * NPTS + nc * 256;
    for (int jj = 0; jj < 8; jj++) {
        int j = w * 8 + jj;
        float mean = g_mean[j], rstd = g_rstd[j], ga = g1[j], be = b1[j];
        float s = 0.0f;
        for (int c8 = 0; c8 < 8; c8++) {
            float y = g_Y[(size_t)j * MTOT + m0 + c8 * 32 + lane];
            s += gelu_fast((y - mean) * rstd * ga + be);
        }
#pragma unroll
        for (int off = 16; off > 0; off >>= 1) s += __shfl_down_sync(0xffffffffu, s, off);
        if (lane == 0) g_hpart[blk * HC + j] = s;
    }
}

__global__ void klabel(const float* __restrict__ w2, float* __restrict__ out) {
    __shared__ float hsum[BB * HC];
    __shared__ float spred[BB * 10];
    int t = threadIdx.x;
    {
        int bb = t >> 6, j = t & 63;
        float s = 0.0f;
        for (int blk = 0; blk < 64; blk++) s += g_hpart[(bb * 64 + blk) * HC + j];
        hsum[t] = s;
    }
    __syncthreads();
    if (t < BB * 10) {
        int b = t / 10, cl = t - b * 10;
        float p = 0.0f;
        for (int j = 0; j < HC; j++) p += hsum[b * HC + j] * w2[j * 10 + cl];
        p *= (1.0f / 16384.0f);
        spred[t] = p;
        out[OFF_PRED + t] = p;
    }
    __syncthreads();
    if (t < BB) {
        float best = spred[t * 10]; int lab = 0;
        for (int c = 1; c < 10; c++) {
            float v = spred[t * 10 + c];
            if (v > best) { best = v; lab = c; }
        }
        g_label[t] = lab;
    }
}

// ---------- EXACT qh = h @ w2[:,label] (sequential j FMA) ----------
__global__ void kq(const float* __restrict__ g1, const float* __restrict__ b1,
                   const float* __restrict__ w2) {
    int m = blockIdx.x * 256 + threadIdx.x;
    int b = m >> 14;
    int lab = g_label[b];
    float acc = 0.0f;
    for (int j = 0; j < HC; j++) {
        float z = bn_exact(g_Y[(size_t)j * MTOT + m], g_mean[j], g_rstd[j],
                           g1[j], b1[j]);
        acc = __fmaf_rn(gelu_exact(z), w2[j * 10 + lab], acc);
    }
    g_qval[m] = acc;
}

// ---------- replicate log_softmax quantization in-place on g_qval ----------
__global__ void klse() {
    int b = blockIdx.x, tid = threadIdx.x;
    __shared__ float smax[256];
    __shared__ float s_mx, s_lse;
    float* qv = g_qval + b * NPTS;
    float mx = -3.402823466e38f;
    for (int i = tid; i < NPTS; i += 256) mx = fmaxf(mx, qv[i]);
    smax[tid] = mx; __syncthreads();
    for (int s = 128; s > 0; s >>= 1) {
        if (tid < s) smax[tid] = fmaxf(smax[tid], smax[tid + s]);
        __syncthreads();
    }
    if (tid == 0) {
        float mxv = smax[0];
        float acc = 0.0f;
        for (int i = 0; i < NPTS; i++)
            acc = __fadd_rn(acc, eigen_expf(__fsub_rn(qv[i], mxv)));
        s_mx = mxv;
        s_lse = eigen_logf(acc);
    }
    __syncthreads();
    float mxv = s_mx, lse = s_lse;
    for (int i = tid; i < NPTS; i += 256)
        qv[i] = __fsub_rn(__fsub_rn(qv[i], mxv), lse);
}

// ---------- top-256 per batch (logp desc, idx asc) ----------
__device__ __forceinline__ unsigned long long make_key(float v, int n) {
    unsigned int u = __float_as_uint(v);
    u = (u & 0x80000000u) ? ~u : (u | 0x80000000u);
    return ((unsigned long long)u << 32) | (unsigned int)(16383 - n);
}

__global__ void ktop(const float* __restrict__ points, float* __restrict__ out) {
    int b = blockIdx.x, tid = threadIdx.x;
    __shared__ int sred[256];
    __shared__ unsigned long long ssel[NQ];
    __shared__ int scnt;
    const float* qv = g_qval + b * NPTS;
    unsigned long long lo = 0ull, hi = 0xFFFFFFFFFFFFFFFFull;
    while (lo < hi) {
        unsigned long long mid = lo + ((hi - lo) >> 1) + 1ull;
        int c = 0;
        for (int n = tid; n < NPTS; n += 256)
            c += (make_key(qv[n], n) >= mid) ? 1 : 0;
        sred[tid] = c; __syncthreads();
        for (int s = 128; s > 0; s >>= 1) {
            if (tid < s) sred[tid] += sred[tid + s];
            __syncthreads();
        }
        int total = sred[0];
        __syncthreads();
        if (total >= NQ) lo = mid; else hi = mid - 1ull;
    }
    if (tid == 0) scnt = 0;
    __syncthreads();
    for (int n = tid; n < NPTS; n += 256) {
        unsigned long long key = make_key(qv[n], n);
        if (key >= lo) { int p = atomicAdd(&scnt, 1); ssel[p] = key; }
    }
    __syncthreads();
    for (int k = 2; k <= NQ; k <<= 1) {
        for (int j = k >> 1; j > 0; j >>= 1) {
            int ixj = tid ^ j;
            if (ixj > tid) {
                unsigned long long a = ssel[tid], c = ssel[ixj];
                bool up = ((tid & k) == 0);
                if ((a > c) == up) { ssel[tid] = c; ssel[ixj] = a; }
            }
            __syncthreads();
        }
    }
    unsigned long long key = ssel[255 - tid];
    int n = 16383 - (int)(unsigned int)(key & 0xFFFFFFFFull);
    g_qidx[b * NQ + tid] = n;
    for (int c = 0; c < 3; c++)
        out[OFF_QUERY + (b * 3 + c) * NQ + tid] =
            points[(size_t)(b * 3 + c) * NPTS + n];
}

__global__ void kgather(const float* __restrict__ feats, float* __restrict__ out) {
    int bc = blockIdx.x;
    int r = threadIdx.x;
    int b = bc >> 8;
    int n = g_qidx[b * NQ + r];
    out[OFF_QF + (size_t)bc * NQ + r] = feats[(size_t)bc * NPTS + n];
}

__global__ void kball(const float* __restrict__ points, float* __restrict__ out) {
    int tid = threadIdx.x;
    int lane = tid & 31;
    int gw = blockIdx.x * 8 + (tid >> 5);
    int b = gw >> 8;
    int nq = g_qidx[gw];
    const float* px = points + (size_t)b * 3 * NPTS;
    float qx = px[nq], qy = px[NPTS + nq], qz = px[2 * NPTS + nq];
    float* o1 = out + OFF_G1 + (size_t)gw * NS1;
    float* o0 = out + OFF_G0 + (size_t)gw * NS0;
    const float R0 = 0.04000000283122062f;  // fl(0.2)^2 in fp32: 0.2f*0.2f
    const float R1 = 0.16000001132488251f;
    int cnt0 = 0, cnt1 = 0, first0 = -1, first1 = -1;
    for (int base = 0; base < NPTS; base += 32) {
        if (cnt0 >= NS0 && cnt1 >= NS1) break;
        int i = base + lane;
        float dx = px[i] - qx;
        float dy = px[NPTS + i] - qy;
        float dz = px[2 * NPTS + i] - qz;
        float sq = __fadd_rn(__fadd_rn(__fmul_rn(dx, dx), __fmul_rn(dy, dy)),
                             __fmul_rn(dz, dz));
        bool in1 = (sq <= R1), in0 = (sq <= R0);
        unsigned m1 = __ballot_sync(0xffffffffu, in1);
        unsigned m0 = __ballot_sync(0xffffffffu, in0);
        unsigned ltm = (lane == 31) ? 0x7fffffffu : ((1u << lane) - 1u);
        if (in1) { int s = cnt1 + __popc(m1 & ltm); if (s < NS1) o1[s] = (float)i; }
        if (in0) { int s = cnt0 + __popc(m0 & ltm); if (s < NS0) o0[s] = (float)i; }
        if (first1 < 0 && m1) first1 = base + __ffs((int)m1) - 1;
        if (first0 < 0 && m0) first0 = base + __ffs((int)m0) - 1;
        cnt1 += __popc(m1); cnt0 += __popc(m0);
    }
    float f1 = (first1 >= 0) ? (float)first1 : (float)(NPTS - 1);
    float f0 = (first0 >= 0) ? (float)first0 : (float)(NPTS - 1);
    for (int s = lane; s < NS1; s += 32) if (s >= cnt1) o1[s] = f1;
    for (int s = lane; s < NS0; s += 32) if (s >= cnt0) o0[s] = f0;
}

extern "C" void kernel_launch(void* const* d_in, const int* in_sizes, int n_in,
                              void* d_out, int out_size) {
    const float* points = (const float*)d_in[0];
    const float* feats  = (const float*)d_in[1];
    const float* w1 = (const float*)d_in[2];
    const float* g1 = (const float*)d_in[3];
    const float* b1 = (const float*)d_in[4];
    const float* w2 = (const float*)d_in[5];
    const float* wm = (const float*)d_in[6];
    const float* gm = (const float*)d_in[7];
    const float* bm = (const float*)d_in[8];
    float* out = (float*)d_out;

    kpack<<<320, 256>>>(w1, wm);
    kgemm<<<dim3(512, 5), 256>>>(feats, out);
    kstats_y<<<2, 32>>>();
    ksum_m<<<256, 256>>>(out);
    knorm<<<16384, 256>>>(out, gm, bm);
    khpart<<<256, 256>>>(g1, b1);
    klabel<<<1, 256>>>(w2, out);
    kq<<<256, 256>>>(g1, b1, w2);
    klse<<<4, 256>>>();
    ktop<<<4, 256>>>(points, out);
    kgather<<<1024, 256>>>(feats, out);
    kball<<<128, 256>>>(points, out);
}

// round 11
// speedup vs baseline: 1.1225x; 1.1225x over previous
#include <cuda_runtime.h>
#include <cstdint>
#include <math.h>

#define BB 4
#define CC 256
#define NPTS 16384
#define MTOT 65536
#define HC 64
#define NOUT 320
#define NQ 256
#define NS0 32
#define NS1 64

#define OFF_QUERY 0
#define OFF_QF    3072
#define OFF_PRED  265216
#define OFF_M     265256
#define OFF_G0    17042472
#define OFF_G1    17075240

__device__ float g_W[CC * NOUT];
__device__ float g_Y[HC * MTOT];    // column-major [col][m]  (for kq/khpart)
__device__ float g_Yt[MTOT * HC];   // row-major [m][col]     (for exact stats)
__device__ float g_mean[NOUT];
__device__ float g_rstd[NOUT];
__device__ float g_hpart[256 * HC];
__device__ int   g_label[BB];
__device__ float g_qval[MTOT];
__device__ float g_exp[MTOT];
__device__ float g_max[BB];
__device__ float g_lse[BB];
__device__ int   g_qidx[BB * NQ];

// ---------- fast gelu (1e-3-tolerance outputs only) ----------
__device__ __forceinline__ float gelu_fast(float x) {
    float x3 = x * x * x;
    float t = tanhf(0.7978845608028654f * (x + 0.044715f * x3));
    return 0.5f * x * (1.0f + t);
}

// ---------- XLA FastTanh (rational, separate mul/add, fdiv) ----------
__device__ __forceinline__ float xla_tanhf(float x) {
    if (fabsf(x) < 0.0004f) return x;
    float xc = fminf(fmaxf(x, -7.90531110763549805f), 7.90531110763549805f);
    float x2 = __fmul_rn(xc, xc);
    float p = -2.76076847742355e-16f;
    p = __fadd_rn(__fmul_rn(p, x2), 2.00018790482477e-13f);
    p = __fadd_rn(__fmul_rn(p, x2), -8.60467152213735e-11f);
    p = __fadd_rn(__fmul_rn(p, x2), 5.12229709037114e-08f);
    p = __fadd_rn(__fmul_rn(p, x2), 1.48572235717979e-05f);
    p = __fadd_rn(__fmul_rn(p, x2), 6.37261928875436e-04f);
    p = __fadd_rn(__fmul_rn(p, x2), 4.89352455891786e-03f);
    float num = __fmul_rn(xc, p);
    float q = 1.19825839466702e-06f;
    q = __fadd_rn(__fmul_rn(q, x2), 1.18534705686654e-04f);
    q = __fadd_rn(__fmul_rn(q, x2), 2.26843463243900e-03f);
    q = __fadd_rn(__fmul_rn(q, x2), 4.89352518554385e-03f);
    return __fdiv_rn(num, q);
}

__device__ __forceinline__ float gelu_exact(float x) {
    float x2 = __fmul_rn(x, x);
    float x3 = __fmul_rn(x2, x);
    float a  = __fadd_rn(x, __fmul_rn(0.044715f, x3));
    float t  = xla_tanhf(__fmul_rn(0.7978845608028654f, a));
    float cdf = __fmul_rn(0.5f, __fadd_rn(1.0f, t));
    return __fmul_rn(x, cdf);
}

__device__ __forceinline__ float bn_exact(float x, float mean, float rstd,
                                          float ga, float be) {
    return __fadd_rn(__fmul_rn(__fmul_rn(__fsub_rn(x, mean), rstd), ga), be);
}

// ---------- Eigen pexp<float> replica ----------
__device__ __forceinline__ float eigen_expf(float x) {
    x = fminf(fmaxf(x, -88.723164f), 88.723164f);
    float m = floorf(__fmaf_rn(x, 1.44269504088896341f, 0.5f));
    float r = __fmaf_rn(m, -0.693359375f, x);
    r = __fmaf_rn(m, 2.12194440e-4f, r);
    float r2 = __fmul_rn(r, r);
    float p = 1.9875691500e-4f;
    p = __fmaf_rn(p, r, 1.3981999507e-3f);
    p = __fmaf_rn(p, r, 8.3334519073e-3f);
    p = __fmaf_rn(p, r, 4.1665795894e-2f);
    p = __fmaf_rn(p, r, 1.6666665459e-1f);
    p = __fmaf_rn(p, r, 5.0000001201e-1f);
    p = __fmaf_rn(p, r2, r);
    p = __fadd_rn(p, 1.0f);
    int mi = (int)m; if (mi < -126) mi = -126; if (mi > 127) mi = 127;
    return __fmul_rn(p, __int_as_float((unsigned)(mi + 127) << 23));
}

// ---------- Eigen plog<float> replica ----------
__device__ __forceinline__ float eigen_logf(float x) {
    int bits = __float_as_int(x);
    float e = (float)(((bits >> 23) & 0xff) - 126);
    float mant = __int_as_float((bits & 0x807fffff) | 0x3f000000);
    if (mant < 0.707106781186547524f) {
        e = __fsub_rn(e, 1.0f);
        mant = __fadd_rn(__fsub_rn(mant, 1.0f), mant);
    } else {
        mant = __fsub_rn(mant, 1.0f);
    }
    float x2 = __fmul_rn(mant, mant);
    float x3 = __fmul_rn(x2, mant);
    float y = 7.0376836292e-2f;
    y = __fmaf_rn(y, mant, -1.1514610310e-1f);
    y = __fmaf_rn(y, mant, 1.1676998740e-1f);
    y = __fmaf_rn(y, mant, -1.2420140846e-1f);
    y = __fmaf_rn(y, mant, 1.4249322787e-1f);
    y = __fmaf_rn(y, mant, -1.6668057665e-1f);
    y = __fmaf_rn(y, mant, 2.0000714765e-1f);
    y = __fmaf_rn(y, mant, -2.4999993993e-1f);
    y = __fmaf_rn(y, mant, 3.3333331174e-1f);
    y = __fmul_rn(y, x3);
    y = __fmaf_rn(e, -2.12194440e-4f, y);
    y = __fsub_rn(y, __fmul_rn(x2, 0.5f));
    float r = __fadd_rn(mant, y);
    return __fmaf_rn(e, 0.693359375f, r);
}

// ---------- pack W = [w1 | wm] ----------
__global__ void kpack(const float* __restrict__ w1, const float* __restrict__ wm) {
    int i = blockIdx.x * 256 + threadIdx.x;
    int c = i / NOUT, k = i - c * NOUT;
    g_W[i] = (k < HC) ? w1[c * HC + k] : wm[c * CC + (k - HC)];
}

// ---------- fused GEMM 65536x320x256, sequential-k FMA chain ----------
__global__ void __launch_bounds__(256) kgemm(const float* __restrict__ feats,
                                             float* __restrict__ out) {
    __shared__ float As[16][128];
    __shared__ __align__(16) float Bs[16][64];
    int bm = blockIdx.x, bn = blockIdx.y;
    int tid = threadIdx.x;
    int b  = bm >> 7;
    int n0 = (bm & 127) << 7;
    const float* Ab = feats + (size_t)b * (CC * NPTS) + n0;
    const float* Wb = g_W + bn * 64;
    int mlane = tid & 15;
    int ngrp  = tid >> 4;
    float acc[8][4];
#pragma unroll
    for (int i = 0; i < 8; i++)
#pragma unroll
        for (int j = 0; j < 4; j++) acc[i][j] = 0.0f;

    for (int kt = 0; kt < CC; kt += 16) {
#pragma unroll
        for (int i = 0; i < 8; i++) {
            int l = tid + i * 256; int k = l >> 7, mm = l & 127;
            As[k][mm] = Ab[(size_t)(kt + k) * NPTS + mm];
        }
#pragma unroll
        for (int i = 0; i < 4; i++) {
            int l = tid + i * 256; int k = l >> 6, nn = l & 63;
            Bs[k][nn] = Wb[(kt + k) * NOUT + nn];
        }
        __syncthreads();
#pragma unroll
        for (int k = 0; k < 16; k++) {
            float a[8];
#pragma unroll
            for (int i = 0; i < 8; i++) a[i] = As[k][mlane + i * 16];
            float4 b4 = *(const float4*)&Bs[k][ngrp * 4];
#pragma unroll
            for (int i = 0; i < 8; i++) {
                acc[i][0] = __fmaf_rn(a[i], b4.x, acc[i][0]);
                acc[i][1] = __fmaf_rn(a[i], b4.y, acc[i][1]);
                acc[i][2] = __fmaf_rn(a[i], b4.z, acc[i][2]);
                acc[i][3] = __fmaf_rn(a[i], b4.w, acc[i][3]);
            }
        }
        __syncthreads();
    }

    int m0 = bm << 7;
    if (bn == 0) {
#pragma unroll
        for (int i = 0; i < 8; i++) {
            int m = m0 + mlane + i * 16;
#pragma unroll
            for (int j = 0; j < 4; j++)
                g_Y[(size_t)(ngrp * 4 + j) * MTOT + m] = acc[i][j];
            // row-major copy for exact stats (coalesced-ish float4)
            float4 v4 = make_float4(acc[i][0], acc[i][1], acc[i][2], acc[i][3]);
            *(float4*)&g_Yt[(size_t)m * HC + ngrp * 4] = v4;
        }
    } else {
        float* mo = out + OFF_M;
#pragma unroll
        for (int i = 0; i < 8; i++) {
            int n = n0 + mlane + i * 16;
#pragma unroll
            for (int j = 0; j < 4; j++) {
                int d = (bn - 1) * 64 + ngrp * 4 + j;
                mo[((size_t)(b * CC + d)) * NPTS + n] = acc[i][j];
            }
        }
    }
}

// ---------- EXACT y-branch stats: sequential two-pass, coalesced over g_Yt ----------
__global__ void kstats_y() {
    int j = threadIdx.x;                 // <<<1, 64>>>, channel j
    float acc = 0.0f;
#pragma unroll 8
    for (int i = 0; i < MTOT; i++)
        acc = __fadd_rn(acc, g_Yt[(size_t)i * HC + j]);
    float mean = __fdiv_rn(acc, 65536.0f);
    float v = 0.0f;
#pragma unroll 8
    for (int i = 0; i < MTOT; i++) {
        float d = __fsub_rn(g_Yt[(size_t)i * HC + j], mean);
        v = __fadd_rn(v, __fmul_rn(d, d));
    }
    float var = __fdiv_rn(v, 65536.0f);
    g_mean[j] = mean;
    g_rstd[j] = __fdiv_rn(1.0f, __fsqrt_rn(__fadd_rn(var, 1e-5f)));
}

// ---------- fast tree stats for m channels (1e-3 tolerance) ----------
__global__ void ksum_m(const float* __restrict__ out) {
    int ch = HC + blockIdx.x;
    int tid = threadIdx.x;
    __shared__ float s1[256], s2[256];
    float a = 0.0f, q = 0.0f;
    int d = ch - HC;
    for (int b = 0; b < BB; b++) {
        const float* p = out + OFF_M + ((size_t)(b * CC + d)) * NPTS;
        for (int i = tid; i < NPTS; i += 256) { float v = p[i]; a += v; q += v * v; }
    }
    s1[tid] = a; s2[tid] = q; __syncthreads();
    for (int s = 128; s > 0; s >>= 1) {
        if (tid < s) { s1[tid] += s1[tid + s]; s2[tid] += s2[tid + s]; }
        __syncthreads();
    }
    if (tid == 0) {
        float mean = s1[0] * (1.0f / 65536.0f);
        float var  = s2[0] * (1.0f / 65536.0f) - mean * mean;
        g_mean[ch] = mean;
        g_rstd[ch] = rsqrtf(var + 1e-5f);
    }
}

// ---------- gelu(BN(m)) in-place ----------
__global__ void knorm(float* __restrict__ out, const float* __restrict__ gm,
                      const float* __restrict__ bm) {
    int i4 = blockIdx.x * 256 + threadIdx.x;
    size_t base = (size_t)i4 * 4;
    int d = (int)((base >> 14) & 255);
    float mean = g_mean[HC + d], rstd = g_rstd[HC + d];
    float ga = gm[d], be = bm[d];
    float* mo = out + OFF_M;
    float4 v = *(float4*)(mo + base);
    v.x = gelu_fast((v.x - mean) * rstd * ga + be);
    v.y = gelu_fast((v.y - mean) * rstd * ga + be);
    v.z = gelu_fast((v.z - mean) * rstd * ga + be);
    v.w = gelu_fast((v.w - mean) * rstd * ga + be);
    *(float4*)(mo + base) = v;
}

// ---------- partial h sums (fast path, preds/label only) ----------
__global__ void khpart(const float* __restrict__ g1, const float* __restrict__ b1) {
    int blk = blockIdx.x;
    int tid = threadIdx.x;
    int lane = tid & 31, w = tid >> 5;
    int b = blk >> 6, nc = blk & 63;
    int m0 = b * NPTS + nc * 256;
    for (int jj = 0; jj < 8; jj++) {
        int j = w * 8 + jj;
        float mean = g_mean[j], rstd = g_rstd[j], ga = g1[j], be = b1[j];
        float s = 0.0f;
        for (int c8 = 0; c8 < 8; c8++) {
            float y = g_Y[(size_t)j * MTOT + m0 + c8 * 32 + lane];
            s += gelu_fast((y - mean) * rstd * ga + be);
        }
#pragma unroll
        for (int off = 16; off > 0; off >>= 1) s += __shfl_down_sync(0xffffffffu, s, off);
        if (lane == 0) g_hpart[blk * HC + j] = s;
    }
}

__global__ void klabel(const float* __restrict__ w2, float* __restrict__ out) {
    __shared__ float hsum[BB * HC];
    __shared__ float spred[BB * 10];
    int t = threadIdx.x;
    {
        int bb = t >> 6, j = t & 63;
        float s = 0.0f;
        for (int blk = 0; blk < 64; blk++) s += g_hpart[(bb * 64 + blk) * HC + j];
        hsum[t] = s;
    }
    __syncthreads();
    if (t < BB * 10) {
        int b = t / 10, cl = t - b * 10;
        float p = 0.0f;
        for (int j = 0; j < HC; j++) p += hsum[b * HC + j] * w2[j * 10 + cl];
        p *= (1.0f / 16384.0f);
        spred[t] = p;
        out[OFF_PRED + t] = p;
    }
    __syncthreads();
    if (t < BB) {
        float best = spred[t * 10]; int lab = 0;
        for (int c = 1; c < 10; c++) {
            float v = spred[t * 10 + c];
            if (v > best) { best = v; lab = c; }
        }
        g_label[t] = lab;
    }
}

// ---------- EXACT qh = h @ w2[:,label] ----------
__global__ void kq(const float* __restrict__ g1, const float* __restrict__ b1,
                   const float* __restrict__ w2) {
    int m = blockIdx.x * 256 + threadIdx.x;
    int b = m >> 14;
    int lab = g_label[b];
    float acc = 0.0f;
    for (int j = 0; j < HC; j++) {
        float z = bn_exact(g_Y[(size_t)j * MTOT + m], g_mean[j], g_rstd[j],
                           g1[j], b1[j]);
        acc = __fmaf_rn(gelu_exact(z), w2[j * 10 + lab], acc);
    }
    g_qval[m] = acc;
}

// ---------- log_softmax replication, parallelized ----------
__global__ void kmax() {
    int b = blockIdx.x, tid = threadIdx.x;
    __shared__ float smax[256];
    const float* qv = g_qval + b * NPTS;
    float mx = -3.402823466e38f;
    for (int i = tid; i < NPTS; i += 256) mx = fmaxf(mx, qv[i]);
    smax[tid] = mx; __syncthreads();
    for (int s = 128; s > 0; s >>= 1) {
        if (tid < s) smax[tid] = fmaxf(smax[tid], smax[tid + s]);
        __syncthreads();
    }
    if (tid == 0) g_max[b] = smax[0];
}

__global__ void kexp() {
    int i = blockIdx.x * 256 + threadIdx.x;   // < 65536
    int b = i >> 14;
    g_exp[i] = eigen_expf(__fsub_rn(g_qval[i], g_max[b]));
}

// serial order-mandated FADD chain only (4 threads, one per batch)
__global__ void kserial() {
    int b = threadIdx.x;                      // <<<1, 4>>>
    if (b >= BB) return;
    const float* e = g_exp + b * NPTS;
    float acc = 0.0f;
#pragma unroll 8
    for (int i = 0; i < NPTS; i++) acc = __fadd_rn(acc, e[i]);
    g_lse[b] = eigen_logf(acc);
}

// ---------- top-256 per batch (logp desc, idx asc) ----------
__device__ __forceinline__ unsigned long long make_key(float v, int n) {
    unsigned int u = __float_as_uint(v);
    u = (u & 0x80000000u) ? ~u : (u | 0x80000000u);
    return ((unsigned long long)u << 32) | (unsigned int)(16383 - n);
}

__global__ void ktop(const float* __restrict__ points, float* __restrict__ out) {
    int b = blockIdx.x, tid = threadIdx.x;
    __shared__ int sred[256];
    __shared__ unsigned long long ssel[NQ];
    __shared__ int scnt;
    const float* qv = g_qval + b * NPTS;
    float mxv = g_max[b], lse = g_lse[b];
    unsigned long long lo = 0ull, hi = 0xFFFFFFFFFFFFFFFFull;
    while (lo < hi) {
        unsigned long long mid = lo + ((hi - lo) >> 1) + 1ull;
        int c = 0;
        for (int n = tid; n < NPTS; n += 256) {
            float lp = __fsub_rn(__fsub_rn(qv[n], mxv), lse);
            c += (make_key(lp, n) >= mid) ? 1 : 0;
        }
        sred[tid] = c; __syncthreads();
        for (int s = 128; s > 0; s >>= 1) {
            if (tid < s) sred[tid] += sred[tid + s];
            __syncthreads();
        }
        int total = sred[0];
        __syncthreads();
        if (total >= NQ) lo = mid; else hi = mid - 1ull;
    }
    if (tid == 0) scnt = 0;
    __syncthreads();
    for (int n = tid; n < NPTS; n += 256) {
        float lp = __fsub_rn(__fsub_rn(qv[n], mxv), lse);
        unsigned long long key = make_key(lp, n);
        if (key >= lo) { int p = atomicAdd(&scnt, 1); ssel[p] = key; }
    }
    __syncthreads();
    for (int k = 2; k <= NQ; k <<= 1) {
        for (int j = k >> 1; j > 0; j >>= 1) {
            int ixj = tid ^ j;
            if (ixj > tid) {
                unsigned long long a = ssel[tid], c = ssel[ixj];
                bool up = ((tid & k) == 0);
                if ((a > c) == up) { ssel[tid] = c; ssel[ixj] = a; }
            }
            __syncthreads();
        }
    }
    unsigned long long key = ssel[255 - tid];
    int n = 16383 - (int)(unsigned int)(key & 0xFFFFFFFFull);
    g_qidx[b * NQ + tid] = n;
    for (int c = 0; c < 3; c++)
        out[OFF_QUERY + (b * 3 + c) * NQ + tid] =
            points[(size_t)(b * 3 + c) * NPTS + n];
}

__global__ void kgather(const float* __restrict__ feats, float* __restrict__ out) {
    int bc = blockIdx.x;
    int r = threadIdx.x;
    int b = bc >> 8;
    int n = g_qidx[b * NQ + r];
    out[OFF_QF + (size_t)bc * NQ + r] = feats[(size_t)bc * NPTS + n];
}

__global__ void kball(const float* __restrict__ points, float* __restrict__ out) {
    int tid = threadIdx.x;
    int lane = tid & 31;
    int gw = blockIdx.x * 8 + (tid >> 5);
    int b = gw >> 8;
    int nq = g_qidx[gw];
    const float* px = points + (size_t)b * 3 * NPTS;
    float qx = px[nq], qy = px[NPTS + nq], qz = px[2 * NPTS + nq];
    float* o1 = out + OFF_G1 + (size_t)gw * NS1;
    float* o0 = out + OFF_G0 + (size_t)gw * NS0;
    const float R0 = 0.04000000283122062f;
    const float R1 = 0.16000001132488251f;
    int cnt0 = 0, cnt1 = 0, first0 = -1, first1 = -1;
    for (int base = 0; base < NPTS; base += 32) {
        if (cnt0 >= NS0 && cnt1 >= NS1) break;
        int i = base + lane;
        float dx = px[i] - qx;
        float dy = px[NPTS + i] - qy;
        float dz = px[2 * NPTS + i] - qz;
        float sq = __fadd_rn(__fadd_rn(__fmul_rn(dx, dx), __fmul_rn(dy, dy)),
                             __fmul_rn(dz, dz));
        bool in1 = (sq <= R1), in0 = (sq <= R0);
        unsigned m1 = __ballot_sync(0xffffffffu, in1);
        unsigned m0 = __ballot_sync(0xffffffffu, in0);
        unsigned ltm = (lane == 31) ? 0x7fffffffu : ((1u << lane) - 1u);
        if (in1) { int s = cnt1 + __popc(m1 & ltm); if (s < NS1) o1[s] = (float)i; }
        if (in0) { int s = cnt0 + __popc(m0 & ltm); if (s < NS0) o0[s] = (float)i; }
        if (first1 < 0 && m1) first1 = base + __ffs((int)m1) - 1;
        if (first0 < 0 && m0) first0 = base + __ffs((int)m0) - 1;
        cnt1 += __popc(m1); cnt0 += __popc(m0);
    }
    float f1 = (first1 >= 0) ? (float)first1 : (float)(NPTS - 1);
    float f0 = (first0 >= 0) ? (float)first0 : (float)(NPTS - 1);
    for (int s = lane; s < NS1; s += 32) if (s >= cnt1) o1[s] = f1;
    for (int s = lane; s < NS0; s += 32) if (s >= cnt0) o0[s] = f0;
}

extern "C" void kernel_launch(void* const* d_in, const int* in_sizes, int n_in,
                              void* d_out, int out_size) {
    const float* points = (const float*)d_in[0];
    const float* feats  = (const float*)d_in[1];
    const float* w1 = (const float*)d_in[2];
    const float* g1 = (const float*)d_in[3];
    const float* b1 = (const float*)d_in[4];
    const float* w2 = (const float*)d_in[5];
    const float* wm = (const float*)d_in[6];
    const float* gm = (const float*)d_in[7];
    const float* bm = (const float*)d_in[8];
    float* out = (float*)d_out;

    kpack<<<320, 256>>>(w1, wm);
    kgemm<<<dim3(512, 5), 256>>>(feats, out);
    kstats_y<<<1, 64>>>();
    ksum_m<<<256, 256>>>(out);
    knorm<<<16384, 256>>>(out, gm, bm);
    khpart<<<256, 256>>>(g1, b1);
    klabel<<<1, 256>>>(w2, out);
    kq<<<256, 256>>>(g1, b1, w2);
    kmax<<<4, 256>>>();
    kexp<<<256, 256>>>();
    kserial<<<1, 4>>>();
    ktop<<<4, 256>>>(points, out);
    kgather<<<1024, 256>>>(feats, out);
    kball<<<128, 256>>>(points, out);
}

// round 12
// speedup vs baseline: 3.1702x; 2.8243x over previous
#include <cuda_runtime.h>
#include <cstdint>
#include <math.h>

#define BB 4
#define CC 256
#define NPTS 16384
#define MTOT 65536
#define HC 64
#define NOUT 320
#define NQ 256
#define NS0 32
#define NS1 64

#define OFF_QUERY 0
#define OFF_QF    3072
#define OFF_PRED  265216
#define OFF_M     265256
#define OFF_G0    17042472
#define OFF_G1    17075240

__device__ float g_W[CC * NOUT];
__device__ float g_Y[HC * MTOT];    // column-major [col][m]  (for kq/khpart)
__device__ float g_Yt[MTOT * HC];   // row-major [m][col]     (for exact stats)
__device__ float g_mean[NOUT];
__device__ float g_rstd[NOUT];
__device__ float g_hpart[256 * HC];
__device__ int   g_label[BB];
__device__ float g_qval[MTOT];
__device__ float g_exp[MTOT];
__device__ float g_max[BB];
__device__ float g_lse[BB];
__device__ int   g_qidx[BB * NQ];
__device__ float g_sink;

// ---------- fast gelu (1e-3-tolerance outputs only) ----------
__device__ __forceinline__ float gelu_fast(float x) {
    float x3 = x * x * x;
    float t = tanhf(0.7978845608028654f * (x + 0.044715f * x3));
    return 0.5f * x * (1.0f + t);
}

// ---------- XLA FastTanh (rational, separate mul/add, fdiv) ----------
__device__ __forceinline__ float xla_tanhf(float x) {
    if (fabsf(x) < 0.0004f) return x;
    float xc = fminf(fmaxf(x, -7.90531110763549805f), 7.90531110763549805f);
    float x2 = __fmul_rn(xc, xc);
    float p = -2.76076847742355e-16f;
    p = __fadd_rn(__fmul_rn(p, x2), 2.00018790482477e-13f);
    p = __fadd_rn(__fmul_rn(p, x2), -8.60467152213735e-11f);
    p = __fadd_rn(__fmul_rn(p, x2), 5.12229709037114e-08f);
    p = __fadd_rn(__fmul_rn(p, x2), 1.48572235717979e-05f);
    p = __fadd_rn(__fmul_rn(p, x2), 6.37261928875436e-04f);
    p = __fadd_rn(__fmul_rn(p, x2), 4.89352455891786e-03f);
    float num = __fmul_rn(xc, p);
    float q = 1.19825839466702e-06f;
    q = __fadd_rn(__fmul_rn(q, x2), 1.18534705686654e-04f);
    q = __fadd_rn(__fmul_rn(q, x2), 2.26843463243900e-03f);
    q = __fadd_rn(__fmul_rn(q, x2), 4.89352518554385e-03f);
    return __fdiv_rn(num, q);
}

__device__ __forceinline__ float gelu_exact(float x) {
    float x2 = __fmul_rn(x, x);
    float x3 = __fmul_rn(x2, x);
    float a  = __fadd_rn(x, __fmul_rn(0.044715f, x3));
    float t  = xla_tanhf(__fmul_rn(0.7978845608028654f, a));
    float cdf = __fmul_rn(0.5f, __fadd_rn(1.0f, t));
    return __fmul_rn(x, cdf);
}

__device__ __forceinline__ float bn_exact(float x, float mean, float rstd,
                                          float ga, float be) {
    return __fadd_rn(__fmul_rn(__fmul_rn(__fsub_rn(x, mean), rstd), ga), be);
}

// ---------- Eigen pexp<float> replica ----------
__device__ __forceinline__ float eigen_expf(float x) {
    x = fminf(fmaxf(x, -88.723164f), 88.723164f);
    float m = floorf(__fmaf_rn(x, 1.44269504088896341f, 0.5f));
    float r = __fmaf_rn(m, -0.693359375f, x);
    r = __fmaf_rn(m, 2.12194440e-4f, r);
    float r2 = __fmul_rn(r, r);
    float p = 1.9875691500e-4f;
    p = __fmaf_rn(p, r, 1.3981999507e-3f);
    p = __fmaf_rn(p, r, 8.3334519073e-3f);
    p = __fmaf_rn(p, r, 4.1665795894e-2f);
    p = __fmaf_rn(p, r, 1.6666665459e-1f);
    p = __fmaf_rn(p, r, 5.0000001201e-1f);
    p = __fmaf_rn(p, r2, r);
    p = __fadd_rn(p, 1.0f);
    int mi = (int)m; if (mi < -126) mi = -126; if (mi > 127) mi = 127;
    return __fmul_rn(p, __int_as_float((unsigned)(mi + 127) << 23));
}

// ---------- Eigen plog<float> replica ----------
__device__ __forceinline__ float eigen_logf(float x) {
    int bits = __float_as_int(x);
    float e = (float)(((bits >> 23) & 0xff) - 126);
    float mant = __int_as_float((bits & 0x807fffff) | 0x3f000000);
    if (mant < 0.707106781186547524f) {
        e = __fsub_rn(e, 1.0f);
        mant = __fadd_rn(__fsub_rn(mant, 1.0f), mant);
    } else {
        mant = __fsub_rn(mant, 1.0f);
    }
    float x2 = __fmul_rn(mant, mant);
    float x3 = __fmul_rn(x2, mant);
    float y = 7.0376836292e-2f;
    y = __fmaf_rn(y, mant, -1.1514610310e-1f);
    y = __fmaf_rn(y, mant, 1.1676998740e-1f);
    y = __fmaf_rn(y, mant, -1.2420140846e-1f);
    y = __fmaf_rn(y, mant, 1.4249322787e-1f);
    y = __fmaf_rn(y, mant, -1.6668057665e-1f);
    y = __fmaf_rn(y, mant, 2.0000714765e-1f);
    y = __fmaf_rn(y, mant, -2.4999993993e-1f);
    y = __fmaf_rn(y, mant, 3.3333331174e-1f);
    y = __fmul_rn(y, x3);
    y = __fmaf_rn(e, -2.12194440e-4f, y);
    y = __fsub_rn(y, __fmul_rn(x2, 0.5f));
    float r = __fadd_rn(mant, y);
    return __fmaf_rn(e, 0.693359375f, r);
}

// ---------- pack W = [w1 | wm] ----------
__global__ void kpack(const float* __restrict__ w1, const float* __restrict__ wm) {
    int i = blockIdx.x * 256 + threadIdx.x;
    int c = i / NOUT, k = i - c * NOUT;
    g_W[i] = (k < HC) ? w1[c * HC + k] : wm[c * CC + (k - HC)];
}

// ---------- fused GEMM 65536x320x256, sequential-k FMA chain ----------
__global__ void __launch_bounds__(256) kgemm(const float* __restrict__ feats,
                                             float* __restrict__ out) {
    __shared__ float As[16][128];
    __shared__ __align__(16) float Bs[16][64];
    int bm = blockIdx.x, bn = blockIdx.y;
    int tid = threadIdx.x;
    int b  = bm >> 7;
    int n0 = (bm & 127) << 7;
    const float* Ab = feats + (size_t)b * (CC * NPTS) + n0;
    const float* Wb = g_W + bn * 64;
    int mlane = tid & 15;
    int ngrp  = tid >> 4;
    float acc[8][4];
#pragma unroll
    for (int i = 0; i < 8; i++)
#pragma unroll
        for (int j = 0; j < 4; j++) acc[i][j] = 0.0f;

    for (int kt = 0; kt < CC; kt += 16) {
#pragma unroll
        for (int i = 0; i < 8; i++) {
            int l = tid + i * 256; int k = l >> 7, mm = l & 127;
            As[k][mm] = Ab[(size_t)(kt + k) * NPTS + mm];
        }
#pragma unroll
        for (int i = 0; i < 4; i++) {
            int l = tid + i * 256; int k = l >> 6, nn = l & 63;
            Bs[k][nn] = Wb[(kt + k) * NOUT + nn];
        }
        __syncthreads();
#pragma unroll
        for (int k = 0; k < 16; k++) {
            float a[8];
#pragma unroll
            for (int i = 0; i < 8; i++) a[i] = As[k][mlane + i * 16];
            float4 b4 = *(const float4*)&Bs[k][ngrp * 4];
#pragma unroll
            for (int i = 0; i < 8; i++) {
                acc[i][0] = __fmaf_rn(a[i], b4.x, acc[i][0]);
                acc[i][1] = __fmaf_rn(a[i], b4.y, acc[i][1]);
                acc[i][2] = __fmaf_rn(a[i], b4.z, acc[i][2]);
                acc[i][3] = __fmaf_rn(a[i], b4.w, acc[i][3]);
            }
        }
        __syncthreads();
    }

    int m0 = bm << 7;
    if (bn == 0) {
#pragma unroll
        for (int i = 0; i < 8; i++) {
            int m = m0 + mlane + i * 16;
#pragma unroll
            for (int j = 0; j < 4; j++)
                g_Y[(size_t)(ngrp * 4 + j) * MTOT + m] = acc[i][j];
            float4 v4 = make_float4(acc[i][0], acc[i][1], acc[i][2], acc[i][3]);
            *(float4*)&g_Yt[(size_t)m * HC + ngrp * 4] = v4;
        }
    } else {
        float* mo = out + OFF_M;
#pragma unroll
        for (int i = 0; i < 8; i++) {
            int n = n0 + mlane + i * 16;
#pragma unroll
            for (int j = 0; j < 4; j++) {
                int d = (bn - 1) * 64 + ngrp * 4 + j;
                mo[((size_t)(b * CC + d)) * NPTS + n] = acc[i][j];
            }
        }
    }
}

// ---------- L2 prefetch of g_Yt (read sweep; condition practically never true) ----------
__global__ void kpref() {
    int i = blockIdx.x * 256 + threadIdx.x;    // 4096 blocks -> 1M float4
    float4 v = *(const float4*)&g_Yt[(size_t)i * 4];
    if (v.x == 1.0e38f && v.y == -1.0e38f) g_sink = v.z;
}

// ---------- EXACT y-branch stats: sequential two-pass, software-pipelined ----------
// thread j = channel j; chain order identical to plain ascending-i loop.
__global__ void __launch_bounds__(64) kstats_y() {
    const int j = threadIdx.x;                 // <<<1, 64>>>
    const float* p = g_Yt + j;                 // element i at p[i*HC]
    const int U = 32, NIT = MTOT / U;          // 2048 iters

    float b0[U], b1[U], b2[U];
    float acc = 0.0f;
    // ---- pass 1: mean ----
#pragma unroll
    for (int u = 0; u < U; u++) b0[u] = p[(size_t)u * HC];
#pragma unroll
    for (int u = 0; u < U; u++) b1[u] = p[(size_t)(U + u) * HC];
    for (int it = 0; it < NIT; it++) {
        if (it + 2 < NIT) {
            const float* q = p + (size_t)(it + 2) * U * HC;
#pragma unroll
            for (int u = 0; u < U; u++) b2[u] = q[(size_t)u * HC];
        }
#pragma unroll
        for (int u = 0; u < U; u++) acc = __fadd_rn(acc, b0[u]);
#pragma unroll
        for (int u = 0; u < U; u++) { b0[u] = b1[u]; b1[u] = b2[u]; }
    }
    float mean = __fdiv_rn(acc, 65536.0f);

    // ---- pass 2: var (data L2-warm from pass 1) ----
    float vac = 0.0f;
#pragma unroll
    for (int u = 0; u < U; u++) b0[u] = p[(size_t)u * HC];
#pragma unroll
    for (int u = 0; u < U; u++) b1[u] = p[(size_t)(U + u) * HC];
    for (int it = 0; it < NIT; it++) {
        if (it + 2 < NIT) {
            const float* q = p + (size_t)(it + 2) * U * HC;
#pragma unroll
            for (int u = 0; u < U; u++) b2[u] = q[(size_t)u * HC];
        }
#pragma unroll
        for (int u = 0; u < U; u++) {
            float d = __fsub_rn(b0[u], mean);
            vac = __fadd_rn(vac, __fmul_rn(d, d));
        }
#pragma unroll
        for (int u = 0; u < U; u++) { b0[u] = b1[u]; b1[u] = b2[u]; }
    }
    float var = __fdiv_rn(vac, 65536.0f);
    g_mean[j] = mean;
    g_rstd[j] = __fdiv_rn(1.0f, __fsqrt_rn(__fadd_rn(var, 1e-5f)));
}

// ---------- fast tree stats for m channels (1e-3 tolerance) ----------
__global__ void ksum_m(const float* __restrict__ out) {
    int ch = HC + blockIdx.x;
    int tid = threadIdx.x;
    __shared__ float s1[256], s2[256];
    float a = 0.0f, q = 0.0f;
    int d = ch - HC;
    for (int b = 0; b < BB; b++) {
        const float* p = out + OFF_M + ((size_t)(b * CC + d)) * NPTS;
        for (int i = tid; i < NPTS; i += 256) { float v = p[i]; a += v; q += v * v; }
    }
    s1[tid] = a; s2[tid] = q; __syncthreads();
    for (int s = 128; s > 0; s >>= 1) {
        if (tid < s) { s1[tid] += s1[tid + s]; s2[tid] += s2[tid + s]; }
        __syncthreads();
    }
    if (tid == 0) {
        float mean = s1[0] * (1.0f / 65536.0f);
        float var  = s2[0] * (1.0f / 65536.0f) - mean * mean;
        g_mean[ch] = mean;
        g_rstd[ch] = rsqrtf(var + 1e-5f);
    }
}

// ---------- gelu(BN(m)) in-place ----------
__global__ void knorm(float* __restrict__ out, const float* __restrict__ gm,
                      const float* __restrict__ bm) {
    int i4 = blockIdx.x * 256 + threadIdx.x;
    size_t base = (size_t)i4 * 4;
    int d = (int)((base >> 14) & 255);
    float mean = g_mean[HC + d], rstd = g_rstd[HC + d];
    float ga = gm[d], be = bm[d];
    float* mo = out + OFF_M;
    float4 v = *(float4*)(mo + base);
    v.x = gelu_fast((v.x - mean) * rstd * ga + be);
    v.y = gelu_fast((v.y - mean) * rstd * ga + be);
    v.z = gelu_fast((v.z - mean) * rstd * ga + be);
    v.w = gelu_fast((v.w - mean) * rstd * ga + be);
    *(float4*)(mo + base) = v;
}

// ---------- partial h sums (fast path, preds/label only) ----------
__global__ void khpart(const float* __restrict__ g1, const float* __restrict__ b1) {
    int blk = blockIdx.x;
    int tid = threadIdx.x;
    int lane = tid & 31, w = tid >> 5;
    int b = blk >> 6, nc = blk & 63;
    int m0 = b * NPTS + nc * 256;
    for (int jj = 0; jj < 8; jj++) {
        int j = w * 8 + jj;
        float mean = g_mean[j], rstd = g_rstd[j], ga = g1[j], be = b1[j];
        float s = 0.0f;
        for (int c8 = 0; c8 < 8; c8++) {
            float y = g_Y[(size_t)j * MTOT + m0 + c8 * 32 + lane];
            s += gelu_fast((y - mean) * rstd * ga + be);
        }
#pragma unroll
        for (int off = 16; off > 0; off >>= 1) s += __shfl_down_sync(0xffffffffu, s, off);
        if (lane == 0) g_hpart[blk * HC + j] = s;
    }
}

__global__ void klabel(const float* __restrict__ w2, float* __restrict__ out) {
    __shared__ float hsum[BB * HC];
    __shared__ float spred[BB * 10];
    int t = threadIdx.x;
    {
        int bb = t >> 6, j = t & 63;
        float s = 0.0f;
        for (int blk = 0; blk < 64; blk++) s += g_hpart[(bb * 64 + blk) * HC + j];
        hsum[t] = s;
    }
    __syncthreads();
    if (t < BB * 10) {
        int b = t / 10, cl = t - b * 10;
        float p = 0.0f;
        for (int j = 0; j < HC; j++) p += hsum[b * HC + j] * w2[j * 10 + cl];
        p *= (1.0f / 16384.0f);
        spred[t] = p;
        out[OFF_PRED + t] = p;
    }
    __syncthreads();
    if (t < BB) {
        float best = spred[t * 10]; int lab = 0;
        for (int c = 1; c < 10; c++) {
            float v = spred[t * 10 + c];
            if (v > best) { best = v; lab = c; }
        }
        g_label[t] = lab;
    }
}

// ---------- EXACT qh = h @ w2[:,label] ----------
__global__ void kq(const float* __restrict__ g1, const float* __restrict__ b1,
                   const float* __restrict__ w2) {
    int m = blockIdx.x * 256 + threadIdx.x;
    int b = m >> 14;
    int lab = g_label[b];
    float acc = 0.0f;
    for (int j = 0; j < HC; j++) {
        float z = bn_exact(g_Y[(size_t)j * MTOT + m], g_mean[j], g_rstd[j],
                           g1[j], b1[j]);
        acc = __fmaf_rn(gelu_exact(z), w2[j * 10 + lab], acc);
    }
    g_qval[m] = acc;
}

// ---------- log_softmax replication, parallelized ----------
__global__ void kmax() {
    int b = blockIdx.x, tid = threadIdx.x;
    __shared__ float smax[256];
    const float* qv = g_qval + b * NPTS;
    float mx = -3.402823466e38f;
    for (int i = tid; i < NPTS; i += 256) mx = fmaxf(mx, qv[i]);
    smax[tid] = mx; __syncthreads();
    for (int s = 128; s > 0; s >>= 1) {
        if (tid < s) smax[tid] = fmaxf(smax[tid], smax[tid + s]);
        __syncthreads();
    }
    if (tid == 0) g_max[b] = smax[0];
}

__global__ void kexp() {
    int i = blockIdx.x * 256 + threadIdx.x;
    int b = i >> 14;
    g_exp[i] = eigen_expf(__fsub_rn(g_qval[i], g_max[b]));
}

// serial order-mandated FADD chain, software-pipelined (4 threads, one per batch)
__global__ void __launch_bounds__(32) kserial() {
    int b = threadIdx.x;                       // <<<1, 4>>>
    if (b >= BB) return;
    const float4* e = (const float4*)(g_exp + b * NPTS);
    const int U4 = 8, NIT = NPTS / (U4 * 4);   // 8 float4 per iter, 512 iters
    float4 b0[U4], b1[U4], b2[U4];
    float acc = 0.0f;
#pragma unroll
    for (int u = 0; u < U4; u++) b0[u] = e[u];
#pragma unroll
    for (int u = 0; u < U4; u++) b1[u] = e[U4 + u];
    for (int it = 0; it < NIT; it++) {
        if (it + 2 < NIT) {
            const float4* q = e + (size_t)(it + 2) * U4;
#pragma unroll
            for (int u = 0; u < U4; u++) b2[u] = q[u];
        }
#pragma unroll
        for (int u = 0; u < U4; u++) {
            acc = __fadd_rn(acc, b0[u].x);
            acc = __fadd_rn(acc, b0[u].y);
            acc = __fadd_rn(acc, b0[u].z);
            acc = __fadd_rn(acc, b0[u].w);
        }
#pragma unroll
        for (int u = 0; u < U4; u++) { b0[u] = b1[u]; b1[u] = b2[u]; }
    }
    g_lse[b] = eigen_logf(acc);
}

// ---------- top-256 per batch (logp desc, idx asc) ----------
__device__ __forceinline__ unsigned long long make_key(float v, int n) {
    unsigned int u = __float_as_uint(v);
    u = (u & 0x80000000u) ? ~u : (u | 0x80000000u);
    return ((unsigned long long)u << 32) | (unsigned int)(16383 - n);
}

__global__ void ktop(const float* __restrict__ points, float* __restrict__ out) {
    int b = blockIdx.x, tid = threadIdx.x;
    __shared__ int sred[256];
    __shared__ unsigned long long ssel[NQ];
    __shared__ int scnt;
    const float* qv = g_qval + b * NPTS;
    float mxv = g_max[b], lse = g_lse[b];
    unsigned long long lo = 0ull, hi = 0xFFFFFFFFFFFFFFFFull;
    while (lo < hi) {
        unsigned long long mid = lo + ((hi - lo) >> 1) + 1ull;
        int c = 0;
        for (int n = tid; n < NPTS; n += 256) {
            float lp = __fsub_rn(__fsub_rn(qv[n], mxv), lse);
            c += (make_key(lp, n) >= mid) ? 1 : 0;
        }
        sred[tid] = c; __syncthreads();
        for (int s = 128; s > 0; s >>= 1) {
            if (tid < s) sred[tid] += sred[tid + s];
            __syncthreads();
        }
        int total = sred[0];
        __syncthreads();
        if (total >= NQ) lo = mid; else hi = mid - 1ull;
    }
    if (tid == 0) scnt = 0;
    __syncthreads();
    for (int n = tid; n < NPTS; n += 256) {
        float lp = __fsub_rn(__fsub_rn(qv[n], mxv), lse);
        unsigned long long key = make_key(lp, n);
        if (key >= lo) { int p = atomicAdd(&scnt, 1); ssel[p] = key; }
    }
    __syncthreads();
    for (int k = 2; k <= NQ; k <<= 1) {
        for (int j = k >> 1; j > 0; j >>= 1) {
            int ixj = tid ^ j;
            if (ixj > tid) {
                unsigned long long a = ssel[tid], c = ssel[ixj];
                bool up = ((tid & k) == 0);
                if ((a > c) == up) { ssel[tid] = c; ssel[ixj] = a; }
            }
            __syncthreads();
        }
    }
    unsigned long long key = ssel[255 - tid];
    int n = 16383 - (int)(unsigned int)(key & 0xFFFFFFFFull);
    g_qidx[b * NQ + tid] = n;
    for (int c = 0; c < 3; c++)
        out[OFF_QUERY + (b * 3 + c) * NQ + tid] =
            points[(size_t)(b * 3 + c) * NPTS + n];
}

__global__ void kgather(const float* __restrict__ feats, float* __restrict__ out) {
    int bc = blockIdx.x;
    int r = threadIdx.x;
    int b = bc >> 8;
    int n = g_qidx[b * NQ + r];
    out[OFF_QF + (size_t)bc * NQ + r] = feats[(size_t)bc * NPTS + n];
}

__global__ void kball(const float* __restrict__ points, float* __restrict__ out) {
    int tid = threadIdx.x;
    int lane = tid & 31;
    int gw = blockIdx.x * 8 + (tid >> 5);
    int b = gw >> 8;
    int nq = g_qidx[gw];
    const float* px = points + (size_t)b * 3 * NPTS;
    float qx = px[nq], qy = px[NPTS + nq], qz = px[2 * NPTS + nq];
    float* o1 = out + OFF_G1 + (size_t)gw * NS1;
    float* o0 = out + OFF_G0 + (size_t)gw * NS0;
    const float R0 = 0.04000000283122062f;
    const float R1 = 0.16000001132488251f;
    int cnt0 = 0, cnt1 = 0, first0 = -1, first1 = -1;
    for (int base = 0; base < NPTS; base += 32) {
        if (cnt0 >= NS0 && cnt1 >= NS1) break;
        int i = base + lane;
        float dx = px[i] - qx;
        float dy = px[NPTS + i] - qy;
        float dz = px[2 * NPTS + i] - qz;
        float sq = __fadd_rn(__fadd_rn(__fmul_rn(dx, dx), __fmul_rn(dy, dy)),
                             __fmul_rn(dz, dz));
        bool in1 = (sq <= R1), in0 = (sq <= R0);
        unsigned m1 = __ballot_sync(0xffffffffu, in1);
        unsigned m0 = __ballot_sync(0xffffffffu, in0);
        unsigned ltm = (lane == 31) ? 0x7fffffffu : ((1u << lane) - 1u);
        if (in1) { int s = cnt1 + __popc(m1 & ltm); if (s < NS1) o1[s] = (float)i; }
        if (in0) { int s = cnt0 + __popc(m0 & ltm); if (s < NS0) o0[s] = (float)i; }
        if (first1 < 0 && m1) first1 = base + __ffs((int)m1) - 1;
        if (first0 < 0 && m0) first0 = base + __ffs((int)m0) - 1;
        cnt1 += __popc(m1); cnt0 += __popc(m0);
    }
    float f1 = (first1 >= 0) ? (float)first1 : (float)(NPTS - 1);
    float f0 = (first0 >= 0) ? (float)first0 : (float)(NPTS - 1);
    for (int s = lane; s < NS1; s += 32) if (s >= cnt1) o1[s] = f1;
    for (int s = lane; s < NS0; s += 32) if (s >= cnt0) o0[s] = f0;
}

extern "C" void kernel_launch(void* const* d_in, const int* in_sizes, int n_in,
                              void* d_out, int out_size) {
    const float* points = (const float*)d_in[0];
    const float* feats  = (const float*)d_in[1];
    const float* w1 = (const float*)d_in[2];
    const float* g1 = (const float*)d_in[3];
    const float* b1 = (const float*)d_in[4];
    const float* w2 = (const float*)d_in[5];
    const float* wm = (const float*)d_in[6];
    const float* gm = (const float*)d_in[7];
    const float* bm = (const float*)d_in[8];
    float* out = (float*)d_out;

    kpack<<<320, 256>>>(w1, wm);
    kgemm<<<dim3(512, 5), 256>>>(feats, out);
    kpref<<<4096, 256>>>();
    kstats_y<<<1, 64>>>();
    ksum_m<<<256, 256>>>(out);
    knorm<<<16384, 256>>>(out, gm, bm);
    khpart<<<256, 256>>>(g1, b1);
    klabel<<<1, 256>>>(w2, out);
    kq<<<256, 256>>>(g1, b1, w2);
    kmax<<<4, 256>>>();
    kexp<<<256, 256>>>();
    kserial<<<1, 32>>>();
    ktop<<<4, 256>>>(points, out);
    kgather<<<1024, 256>>>(feats, out);
    kball<<<128, 256>>>(points, out);
}